// round 16
// baseline (speedup 1.0000x reference)
#include <cuda_runtime.h>
#include <cuda_fp16.h>
#include <cstdint>

#define N_NODES 100000
#define N_EDGES 1600000
#define E_TOT   (N_EDGES + N_NODES)   // self loops appended
#define N_GRAPHS 1024
#define EPS_BN 1e-5f
#define SCAN_B 98                      // ceil(N_NODES / 1024)
#define FILL_B ((E_TOT + 255) / 256)   // 6642
#define G1B    ((N_NODES + 7) / 8)     // 12500
#define FULLM 0xffffffffu
#define LOG2E 1.4426950408889634f

// ----------------------------- scratch (device globals) -----------------------------
__device__ int    g_batch[N_NODES];
__device__ int    g_deg[N_NODES];      // zero-initialized; scan re-zeroes after use
__device__ int    g_off[N_NODES + 1];
__device__ int    g_cur[N_NODES];
__device__ int    g_csr[E_TOT];
__device__ volatile unsigned g_agg[SCAN_B];
__device__ __half g_hlinh[N_NODES * 128];  // post-GEMM features, fp16 (attn gather input)
__device__ __half g_feath[N_NODES * 128];  // attn output layers 1-2, fp16 (BN/gemm input)
__device__ float  g_feat[N_NODES * 64];    // attn output layer 3, fp32 (pool input)
__device__ float  g_als[N_NODES * 4];      // pre-scaled by log2(e)
__device__ float  g_ald[N_NODES * 4];      // pre-scaled by log2(e)
__device__ float  g_bnsum[256];            // [0:128) sum, [128:256) sumsq

// ----------------------------- utility -----------------------------
__device__ __forceinline__ float ex2f(float x) {
    float r; asm("ex2.approx.f32 %0, %1;" : "=f"(r) : "f"(x)); return r;
}
__device__ __forceinline__ float eluf(float v) {
    return v > 0.f ? v : ex2f(v * LOG2E) - 1.f;
}
__device__ __forceinline__ float lrelu(float v) { return fmaxf(v, 0.2f * v); }
__device__ __forceinline__ unsigned long long pack2(float x, float y) {
    unsigned long long r;
    asm("mov.b64 %0, {%1, %2};" : "=l"(r) : "f"(x), "f"(y));
    return r;
}
__device__ __forceinline__ float2 unpack2(unsigned long long v) {
    float2 r;
    asm("mov.b64 {%0, %1}, %2;" : "=f"(r.x), "=f"(r.y) : "l"(v));
    return r;
}
#define FMA_F32X2(acc, a, b) \
    asm("fma.rn.f32x2 %0, %1, %2, %0;" : "+l"(acc) : "l"(a), "l"(b))

__device__ __forceinline__ uint32_t smem_u32(const void* p) {
    return (uint32_t)__cvta_generic_to_shared(p);
}
__device__ __forceinline__ void ldmatrix_x4(uint32_t* r, uint32_t addr) {
    asm volatile("ldmatrix.sync.aligned.m8n8.x4.shared.b16 {%0,%1,%2,%3}, [%4];"
                 : "=r"(r[0]), "=r"(r[1]), "=r"(r[2]), "=r"(r[3]) : "r"(addr));
}
__device__ __forceinline__ void ldmatrix_x2t(uint32_t& b0, uint32_t& b1, uint32_t addr) {
    asm volatile("ldmatrix.sync.aligned.m8n8.x2.trans.shared.b16 {%0,%1}, [%2];"
                 : "=r"(b0), "=r"(b1) : "r"(addr));
}
__device__ __forceinline__ void mma16816(float& d0, float& d1, float& d2, float& d3,
                                         const uint32_t* a, uint32_t b0, uint32_t b1) {
    asm volatile("mma.sync.aligned.m16n8k16.row.col.f32.f16.f16.f32 "
                 "{%0,%1,%2,%3}, {%4,%5,%6,%7}, {%8,%9}, {%0,%1,%2,%3};"
                 : "+f"(d0), "+f"(d1), "+f"(d2), "+f"(d3)
                 : "r"(a[0]), "r"(a[1]), "r"(a[2]), "r"(a[3]), "r"(b0), "r"(b1));
}

// Per-block dtype detect + edge decode (int64 with values < 2^31: odd int32 words are 0).
__device__ __forceinline__ int detect_is64_block(const void* ei, int i) {
    __shared__ int s_is64;
    if (threadIdx.x == 0) s_is64 = 1;
    __syncthreads();
    if (i < N_EDGES) {
        if (((const int*)ei)[2 * i + 1] != 0) s_is64 = 0;   // race-benign
    }
    __syncthreads();
    return s_is64;
}
__device__ __forceinline__ void decode_edge(const void* ei, int i, int is64, int& s, int& d) {
    if (i < N_EDGES) {
        if (is64) {
            s = (int)((const long long*)ei)[i];
            d = (int)((const long long*)ei)[N_EDGES + i];
        } else {
            s = ((const int*)ei)[i];
            d = ((const int*)ei)[N_EDGES + i];
        }
    } else {
        s = d = i - N_EDGES;
    }
}

// ----------------------------- count: decode ei directly, degree + batch --------------------
__global__ void count_kernel(const void* ei, const void* batch) {
    int i = blockIdx.x * 256 + threadIdx.x;
    int is64 = detect_is64_block(ei, i);
    if (blockIdx.x == 0 && threadIdx.x < SCAN_B) g_agg[threadIdx.x] = 0u;
    if (i < E_TOT) {
        int s, d;
        decode_edge(ei, i, is64, s, d);
        (void)s;
        atomicAdd(&g_deg[d], 1);
    }
    if (i < N_NODES) {
        g_batch[i] = is64 ? (int)((const long long*)batch)[i] : ((const int*)batch)[i];
    }
}

// ----------------------------- single-pass exclusive scan (decoupled lookback) --------------
__global__ void scan_onepass() {
    __shared__ int wsum[32];
    __shared__ int part[128];
    int b = blockIdx.x, t = threadIdx.x;
    int i = b * 1024 + t;
    int d = (i < N_NODES) ? g_deg[i] : 0;
    int lane = t & 31, wid = t >> 5;
    int v = d;
#pragma unroll
    for (int o = 1; o < 32; o <<= 1) {
        int u = __shfl_up_sync(FULLM, v, o);
        if (lane >= o) v += u;
    }
    if (lane == 31) wsum[wid] = v;
    if (t < 128) part[t] = 0;
    __syncthreads();
    if (t < 32) {
        int w = wsum[t];
#pragma unroll
        for (int o = 1; o < 32; o <<= 1) {
            int u = __shfl_up_sync(FULLM, w, o);
            if (t >= o) w += u;
        }
        wsum[t] = w;
    }
    __syncthreads();
    int incl = v + (wid ? wsum[wid - 1] : 0);
    int total = wsum[31];
    if (t == 0) atomicExch((unsigned*)&g_agg[b], ((unsigned)total) | 0x80000000u);
    if (t < b) {
        unsigned x;
        do { x = g_agg[t]; } while (!(x & 0x80000000u));
        part[t] = (int)(x & 0x7fffffffu);
    }
    __syncthreads();
    if (t < 64) part[t] += part[t + 64]; __syncthreads();
    if (t < 32) part[t] += part[t + 32]; __syncthreads();
    if (t < 16) part[t] += part[t + 16]; __syncthreads();
    if (t < 8)  part[t] += part[t + 8];  __syncthreads();
    if (t < 4)  part[t] += part[t + 4];  __syncthreads();
    if (t < 2)  part[t] += part[t + 2];  __syncthreads();
    if (t < 1)  part[t] += part[t + 1];  __syncthreads();
    int base = part[0];
    if (i < N_NODES) {
        int excl = base + incl - d;
        g_off[i] = excl;
        g_cur[i] = excl;
        g_deg[i] = 0;
    }
    if (b == 0 && t == 0) g_off[N_NODES] = E_TOT;
}

// ----------------------------- fused CSR-fill (direct ei decode) + layer-1 GEMM -------------
__global__ void fill_gemm1_kernel(const void* ei,
                                  const float* __restrict__ x, const float* __restrict__ W1,
                                  const float* __restrict__ aS, const float* __restrict__ aD) {
    if (blockIdx.x < FILL_B) {
        int i = blockIdx.x * 256 + threadIdx.x;
        int is64 = detect_is64_block(ei, i);
        if (i < E_TOT) {
            int s, d;
            decode_edge(ei, i, is64, s, d);
            int p = atomicAdd(&g_cur[d], 1);
            g_csr[p] = s;
        }
        return;
    }
    int node = (blockIdx.x - FILL_B) * 8 + (threadIdx.x >> 5);
    int lane = threadIdx.x & 31;
    if (node >= N_NODES) return;
    float acc[4] = {0.f, 0.f, 0.f, 0.f};
    const float* xr = x + node * 5;
#pragma unroll
    for (int k = 0; k < 5; k++) {
        float xv = __ldg(&xr[k]);
        float4 w = __ldg((const float4*)(W1 + k * 128 + lane * 4));
        acc[0] += xv * w.x; acc[1] += xv * w.y; acc[2] += xv * w.z; acc[3] += xv * w.w;
    }
    __half2 h0 = __floats2half2_rn(acc[0], acc[1]);
    __half2 h1 = __floats2half2_rn(acc[2], acc[3]);
    uint2 st;
    st.x = *(unsigned*)&h0; st.y = *(unsigned*)&h1;
    *(uint2*)(g_hlinh + node * 128 + lane * 4) = st;
    float pS = 0.f, pD = 0.f;
#pragma unroll
    for (int j = 0; j < 4; j++) {
        pS += acc[j] * __ldg(&aS[lane * 4 + j]);
        pD += acc[j] * __ldg(&aD[lane * 4 + j]);
    }
#pragma unroll
    for (int o = 1; o < 8; o <<= 1) {
        pS += __shfl_xor_sync(FULLM, pS, o);
        pD += __shfl_xor_sync(FULLM, pD, o);
    }
    if ((lane & 7) == 0) {
        int h = lane >> 3;
        g_als[node * 4 + h] = pS * LOG2E;
        g_ald[node * 4 + h] = pD * LOG2E;
    }
}

// ----------------------------- 128 -> OUTC GEMM via HMMA (tensor cores) ----------------------
template <int OUTC>
__global__ void __launch_bounds__(256) gemm_hmma(
        const float* __restrict__ W,
        const float* __restrict__ aS, const float* __restrict__ aD,
        const float* __restrict__ bnG, const float* __restrict__ bnBe) {
    constexpr int NT = OUTC / 8;
    constexpr int H  = (OUTC == 128) ? 4 : 1;
    constexpr int SA_STR = 136;
    constexpr int SB_STR = OUTC + 8;

    extern __shared__ char smem[];
    __half* sA = (__half*)smem;
    __half* sB = sA + 128 * SA_STR;
    float* sScale = (float*)(sB + 128 * SB_STR);
    float* sShift = sScale + 128;
    float* sAS = sShift + 128;
    float* sAD = sAS + 128;

    int t = threadIdx.x;
    int warp = t >> 5, lane = t & 31;
    int nodeBase = blockIdx.x * 128;

    if (t < 128) {
        const float invN = 1.f / (float)N_NODES;
        float mu = g_bnsum[t] * invN;
        float var = g_bnsum[128 + t] * invN - mu * mu;
        float rs = rsqrtf(var + EPS_BN);
        float sc = rs * __ldg(&bnG[t]);
        sScale[t] = sc;
        sShift[t] = __ldg(&bnBe[t]) - mu * sc;
    }
    if (t < OUTC) {
        sAS[t] = __ldg(&aS[t]);
        sAD[t] = __ldg(&aD[t]);
    }
    __syncthreads();

#pragma unroll
    for (int j = 0; j < 64; j++) {
        int idx = t + j * 256;
        int row = idx >> 7, col = idx & 127;
        int node = nodeBase + row;
        float v = 0.f;
        if (node < N_NODES)
            v = eluf(__half2float(g_feath[node * 128 + col]) * sScale[col] + sShift[col]);
        sA[row * SA_STR + col] = __float2half_rn(v);
    }
#pragma unroll
    for (int j = 0; j < (128 * OUTC) / 256; j++) {
        int idx = t + j * 256;
        int k = idx / OUTC, n = idx % OUTC;
        sB[k * SB_STR + n] = __float2half_rn(__ldg(&W[idx]));
    }
    __syncthreads();

    uint32_t afr[8][4];
    {
        int arow = warp * 16 + (lane & 15);
        int acol = (lane >> 4) << 3;
#pragma unroll
        for (int k8 = 0; k8 < 8; k8++) {
            uint32_t addr = smem_u32(&sA[arow * SA_STR + k8 * 16 + acol]);
            ldmatrix_x4(afr[k8], addr);
        }
    }

    float sS0[H], sS8[H], sD0[H], sD8[H];
#pragma unroll
    for (int h = 0; h < H; h++) { sS0[h] = 0.f; sS8[h] = 0.f; sD0[h] = 0.f; sD8[h] = 0.f; }

    int r = lane >> 2;
    int n0 = nodeBase + warp * 16 + r;
    int brow = lane & 15;

#pragma unroll
    for (int nt = 0; nt < NT; nt++) {
        float d0 = 0.f, d1 = 0.f, d2 = 0.f, d3 = 0.f;
#pragma unroll
        for (int k8 = 0; k8 < 8; k8++) {
            uint32_t b0, b1;
            uint32_t addr = smem_u32(&sB[(k8 * 16 + brow) * SB_STR + nt * 8]);
            ldmatrix_x2t(b0, b1, addr);
            mma16816(d0, d1, d2, d3, afr[k8], b0, b1);
        }
        int c = nt * 8 + 2 * (lane & 3);
        if (n0 < N_NODES)
            *(__half2*)(g_hlinh + (size_t)n0 * OUTC + c) = __floats2half2_rn(d0, d1);
        if (n0 + 8 < N_NODES)
            *(__half2*)(g_hlinh + (size_t)(n0 + 8) * OUTC + c) = __floats2half2_rn(d2, d3);
        int h = (OUTC == 128) ? (nt >> 2) : 0;
        float as0 = sAS[c], as1 = sAS[c + 1];
        float ad0 = sAD[c], ad1 = sAD[c + 1];
        sS0[h] += d0 * as0 + d1 * as1;
        sS8[h] += d2 * as0 + d3 * as1;
        sD0[h] += d0 * ad0 + d1 * ad1;
        sD8[h] += d2 * ad0 + d3 * ad1;
    }

#pragma unroll
    for (int h = 0; h < H; h++) {
#pragma unroll
        for (int o = 1; o < 4; o <<= 1) {
            sS0[h] += __shfl_xor_sync(FULLM, sS0[h], o);
            sS8[h] += __shfl_xor_sync(FULLM, sS8[h], o);
            sD0[h] += __shfl_xor_sync(FULLM, sD0[h], o);
            sD8[h] += __shfl_xor_sync(FULLM, sD8[h], o);
        }
    }
    if ((lane & 3) == 0) {
        if (n0 < N_NODES) {
#pragma unroll
            for (int h = 0; h < H; h++) {
                g_als[n0 * H + h] = sS0[h] * LOG2E;
                g_ald[n0 * H + h] = sD0[h] * LOG2E;
            }
        }
        if (n0 + 8 < N_NODES) {
#pragma unroll
            for (int h = 0; h < H; h++) {
                g_als[(n0 + 8) * H + h] = sS8[h] * LOG2E;
                g_ald[(n0 + 8) * H + h] = sD8[h] * LOG2E;
            }
        }
    }
}

// ----------------------------- attn layers 1-2: quarter-warp, 4 edges/step (FIXED) -----------
// Lane = grp*8 + li; group grp owns edge slot grp; lane li carries channels [li*16, li*16+16).
// FIX vs R15: butterfly-reduce ALL 16 channel accumulators across the 4 groups FIRST
// (lanes with equal li), THEN select the grp-specific 4-channel slice for writing.
__global__ void __launch_bounds__(128, 10) attn128_kernel(const float* __restrict__ bias) {
    if (blockIdx.x == 0 && threadIdx.x < 128) {
        g_bnsum[threadIdx.x] = 0.f;
        g_bnsum[threadIdx.x + 128] = 0.f;
    }
    int node = (blockIdx.x * blockDim.x + threadIdx.x) >> 5;
    int lane = threadIdx.x & 31;
    if (node >= N_NODES) return;
    const int grp = lane >> 3;   // edge slot 0..3
    const int li = lane & 7;     // channel group: 16 channels
    const int h0 = li >> 1;      // head

    float ad = g_ald[node * 4 + h0];
    float s = 0.f;
    unsigned long long acc2[8];
#pragma unroll
    for (int j = 0; j < 8; j++) acc2[j] = 0ull;

    const char* fb = (const char*)g_hlinh + li * 32;   // bytes
    const float* ab = g_als + h0;

    int beg = g_off[node], end = g_off[node + 1];
    int i = beg;
    // ---- full batches: 8 edges = 2 guard-free 4-edge steps ----
    for (; i + 8 <= end; i += 8) {
        int src[2]; float al[2];
        uint4 qa[2], qb[2];
#pragma unroll
        for (int t = 0; t < 2; t++) src[t] = __ldg(&g_csr[i + 4 * t + grp]);
#pragma unroll
        for (int t = 0; t < 2; t++) al[t] = __ldg(ab + src[t] * 4);
#pragma unroll
        for (int t = 0; t < 2; t++) {
            const char* p = fb + (size_t)src[t] * 256;
            qa[t] = *(const uint4*)p;
            qb[t] = *(const uint4*)(p + 16);
        }
#pragma unroll
        for (int t = 0; t < 2; t++) {
            float p = ex2f(lrelu(al[t] + ad));
            s += p;
            unsigned long long pk = pack2(p, p);
            const __half2* ha = (const __half2*)&qa[t];
            const __half2* hb = (const __half2*)&qb[t];
#pragma unroll
            for (int j = 0; j < 4; j++) {
                float2 f = __half22float2(ha[j]);
                FMA_F32X2(acc2[j], pk, pack2(f.x, f.y));
            }
#pragma unroll
            for (int j = 0; j < 4; j++) {
                float2 f = __half22float2(hb[j]);
                FMA_F32X2(acc2[4 + j], pk, pack2(f.x, f.y));
            }
        }
    }
    // ---- tail: 4-edge steps with clamped index + zeroed p ----
    for (; i < end; i += 4) {
        int e = i + grp;
        bool valid = e < end;
        int src = __ldg(&g_csr[valid ? e : end - 1]);
        float a = __ldg(ab + src * 4);
        float p = ex2f(lrelu(a + ad));
        p = valid ? p : 0.f;
        s += p;
        unsigned long long pk = pack2(p, p);
        const char* fp = fb + (size_t)src * 256;
        uint4 qa = *(const uint4*)fp;
        uint4 qb = *(const uint4*)(fp + 16);
        const __half2* ha = (const __half2*)&qa;
        const __half2* hb = (const __half2*)&qb;
#pragma unroll
        for (int j = 0; j < 4; j++) {
            float2 f = __half22float2(ha[j]);
            FMA_F32X2(acc2[j], pk, pack2(f.x, f.y));
        }
#pragma unroll
        for (int j = 0; j < 4; j++) {
            float2 f = __half22float2(hb[j]);
            FMA_F32X2(acc2[4 + j], pk, pack2(f.x, f.y));
        }
    }

    // combine 4 edge-groups (lanes with equal li share channels & head)
    s += __shfl_xor_sync(FULLM, s, 8);
    s += __shfl_xor_sync(FULLM, s, 16);
    float inv = 1.f / (s + 1e-16f);

    // FIX: reduce all 16 channels across groups BEFORE selecting this lane's slice.
    float accf[16];
#pragma unroll
    for (int j = 0; j < 8; j++) {
        float2 f = unpack2(acc2[j]);
        accf[2 * j] = f.x;
        accf[2 * j + 1] = f.y;
    }
#pragma unroll
    for (int k = 0; k < 16; k++) {
        accf[k] += __shfl_xor_sync(FULLM, accf[k], 8);
        accf[k] += __shfl_xor_sync(FULLM, accf[k], 16);
    }

    // lane writes channels [li*16 + grp*4, +4) = accf[4*grp .. 4*grp+3]
    int cb = li * 16 + grp * 4;
    float4 bv = __ldg((const float4*)(bias + cb));
    float o0 = accf[4 * grp + 0] * inv + bv.x;
    float o1 = accf[4 * grp + 1] * inv + bv.y;
    float o2 = accf[4 * grp + 2] * inv + bv.z;
    float o3 = accf[4 * grp + 3] * inv + bv.w;
    __half2 ha = __floats2half2_rn(o0, o1);
    __half2 hb = __floats2half2_rn(o2, o3);
    uint2 st;
    st.x = *(unsigned*)&ha; st.y = *(unsigned*)&hb;
    *(uint2*)(g_feath + (size_t)node * 128 + cb) = st;
}

// ----------------------------- attn layer 3 (R12 proven path: 2 edges/step, K=4) -------------
__global__ void __launch_bounds__(128, 12) attn64_kernel(const float* __restrict__ bias) {
    constexpr int HC = 64;
    constexpr int K = 4, KP = 2;
    int node = (blockIdx.x * blockDim.x + threadIdx.x) >> 5;
    int lane = threadIdx.x & 31;
    if (node >= N_NODES) return;
    const int sub = lane >> 4;
    const int li = lane & 15;

    float ad = g_ald[node];
    float s = 0.f;
    unsigned long long acc2[KP];
#pragma unroll
    for (int j = 0; j < KP; j++) acc2[j] = 0ull;

    const char* fb = (const char*)g_hlinh + li * (K * 2);
    const float* ab = g_als;

    int beg = g_off[node], end = g_off[node + 1];
    int i = beg;
    for (; i + 8 <= end; i += 8) {
        int src[4]; float al[4]; uint2 q2[4];
#pragma unroll
        for (int t = 0; t < 4; t++) src[t] = __ldg(&g_csr[i + 2 * t + sub]);
#pragma unroll
        for (int t = 0; t < 4; t++) al[t] = __ldg(ab + src[t]);
#pragma unroll
        for (int t = 0; t < 4; t++) q2[t] = *(const uint2*)(fb + (size_t)src[t] * (HC * 2));
#pragma unroll
        for (int t = 0; t < 4; t++) {
            float p = ex2f(lrelu(al[t] + ad));
            s += p;
            unsigned long long pk = pack2(p, p);
            const __half2* hq = (const __half2*)&q2[t];
#pragma unroll
            for (int j = 0; j < KP; j++) {
                float2 f = __half22float2(hq[j]);
                FMA_F32X2(acc2[j], pk, pack2(f.x, f.y));
            }
        }
    }
    for (; i < end; i += 2) {
        int idx = i + sub;
        bool valid = idx < end;
        int src = __ldg(&g_csr[valid ? idx : end - 1]);
        float a = __ldg(ab + src);
        float p = ex2f(lrelu(a + ad));
        p = valid ? p : 0.f;
        s += p;
        unsigned long long pk = pack2(p, p);
        uint2 q2 = *(const uint2*)(fb + (size_t)src * (HC * 2));
        const __half2* hq = (const __half2*)&q2;
#pragma unroll
        for (int j = 0; j < KP; j++) {
            float2 f = __half22float2(hq[j]);
            FMA_F32X2(acc2[j], pk, pack2(f.x, f.y));
        }
    }

    s += __shfl_xor_sync(FULLM, s, 16);
    float accf[K];
#pragma unroll
    for (int j = 0; j < KP; j++) {
        float2 f = unpack2(acc2[j]);
        f.x += __shfl_xor_sync(FULLM, f.x, 16);
        f.y += __shfl_xor_sync(FULLM, f.y, 16);
        accf[2 * j] = f.x;
        accf[2 * j + 1] = f.y;
    }
    float inv = 1.f / (s + 1e-16f);
    int cb = li * 4 + sub * 2;
    float2 bv = __ldg((const float2*)(bias + cb));
    float2 o;
    o.x = eluf((sub ? accf[2] : accf[0]) * inv + bv.x);
    o.y = eluf((sub ? accf[3] : accf[1]) * inv + bv.y);
    *(float2*)(g_feat + (size_t)node * HC + cb) = o;
}

// ----------------------------- batch norm stats (fp16 input; bnsum zeroed by attn) ----------
__global__ void bnstats_kernel() {
    int c = threadIdx.x;  // 128
    int n0 = blockIdx.x * 128;
    float s = 0.f, sq = 0.f;
    for (int r = 0; r < 128; r++) {
        int n = n0 + r;
        if (n < N_NODES) {
            float v = __half2float(g_feath[n * 128 + c]);
            s += v;
            sq += v * v;
        }
    }
    atomicAdd(&g_bnsum[c], s);
    atomicAdd(&g_bnsum[128 + c], sq);
}

// ----------------------------- fused pooling + classifier (batch sorted) ---------------------
__device__ __forceinline__ int lower_bound_batch(int key) {
    int lo = 0, hi = N_NODES;
    while (lo < hi) {
        int mid = (lo + hi) >> 1;
        if (g_batch[mid] < key) lo = mid + 1;
        else hi = mid;
    }
    return lo;
}

__global__ void pool_final_kernel(const float* __restrict__ fc1w, const float* __restrict__ fc1b,
                                  const float* __restrict__ fc2w, const float* __restrict__ fc2b,
                                  float* __restrict__ out) {
    int gidx = blockIdx.x;
    __shared__ int se[2];
    if (threadIdx.x < 2) se[threadIdx.x] = lower_bound_batch(gidx + threadIdx.x);
    __syncthreads();
    int beg = se[0], end = se[1];
    int c = threadIdx.x & 63, sl = threadIdx.x >> 6;
    float sum = 0.f, mx = __int_as_float(0xff800000);
    for (int n = beg + sl; n < end; n += 2) {
        float v = g_feat[n * 64 + c];
        sum += v;
        mx = fmaxf(mx, v);
    }
    __shared__ float shs[128], shm[128], hg[128];
    shs[threadIdx.x] = sum;
    shm[threadIdx.x] = mx;
    __syncthreads();
    if (sl == 0) {
        sum += shs[64 + c];
        mx = fmaxf(mx, shm[64 + c]);
        int cnt = end - beg;
        hg[c] = (cnt > 0) ? sum / (float)cnt : 0.f;
        hg[64 + c] = (cnt > 0) ? mx : 0.f;
    }
    __syncthreads();
    __shared__ float warpsum[2];
    if (threadIdx.x < 64) {
        int c2 = threadIdx.x;
        float acc = __ldg(&fc1b[c2]);
#pragma unroll 8
        for (int k = 0; k < 128; k++) acc += hg[k] * __ldg(&fc1w[k * 64 + c2]);
        float z = eluf(acc);
        float part = z * __ldg(&fc2w[c2]);
#pragma unroll
        for (int off = 16; off; off >>= 1) part += __shfl_xor_sync(FULLM, part, off);
        if ((c2 & 31) == 0) warpsum[c2 >> 5] = part;
    }
    __syncthreads();
    if (threadIdx.x == 0) out[gidx] = warpsum[0] + warpsum[1] + __ldg(&fc2b[0]);
}

// ----------------------------- launch -----------------------------
extern "C" void kernel_launch(void* const* d_in, const int* in_sizes, int n_in,
                              void* d_out, int out_size) {
    const float* x      = (const float*)d_in[0];
    const void*  ei     = d_in[1];
    const void*  batch  = d_in[2];
    const float* W1     = (const float*)d_in[3];
    const float* a1_src = (const float*)d_in[4];
    const float* a1_dst = (const float*)d_in[5];
    const float* b1     = (const float*)d_in[6];
    const float* g1     = (const float*)d_in[7];
    const float* be1    = (const float*)d_in[8];
    const float* W2     = (const float*)d_in[9];
    const float* a2_src = (const float*)d_in[10];
    const float* a2_dst = (const float*)d_in[11];
    const float* b2     = (const float*)d_in[12];
    const float* g2     = (const float*)d_in[13];
    const float* be2    = (const float*)d_in[14];
    const float* W3     = (const float*)d_in[15];
    const float* a3_src = (const float*)d_in[16];
    const float* a3_dst = (const float*)d_in[17];
    const float* b3     = (const float*)d_in[18];
    const float* fc1_w  = (const float*)d_in[19];
    const float* fc1_b  = (const float*)d_in[20];
    const float* fc2_w  = (const float*)d_in[21];
    const float* fc2_b  = (const float*)d_in[22];
    float* out = (float*)d_out;

    const int ATTN_B = (N_NODES + 3) / 4;   // 128-thr blocks, 4 warps = 4 nodes/block
    const int HGB = (N_NODES + 127) / 128;

    const int SMEM2 = (128 * 136 + 128 * (128 + 8)) * 2 + 4 * 128 * 4;  // 71680
    const int SMEM3 = (128 * 136 + 128 * (64 + 8)) * 2 + 4 * 128 * 4;   // 55296
    cudaFuncSetAttribute(gemm_hmma<128>, cudaFuncAttributeMaxDynamicSharedMemorySize, SMEM2);
    cudaFuncSetAttribute(gemm_hmma<64>,  cudaFuncAttributeMaxDynamicSharedMemorySize, SMEM3);

    // 1: degree count + batch convert (direct ei decode; +agg reset)
    count_kernel<<<FILL_B, 256>>>(ei, batch);
    // 2: single-pass offsets scan (+deg re-zero)
    scan_onepass<<<SCAN_B, 1024>>>();
    // 3: CSR fill (direct ei decode) + layer-1 GEMM
    fill_gemm1_kernel<<<FILL_B + G1B, 256>>>(ei, x, W1, a1_src, a1_dst);
    // 4: attn layer 1  <-- ncu capture slot
    attn128_kernel<<<ATTN_B, 128>>>(b1);
    // 5: BN1 stats
    bnstats_kernel<<<HGB, 128>>>();
    // 6-7: layer 2
    gemm_hmma<128><<<HGB, 256, SMEM2>>>(W2, a2_src, a2_dst, g1, be1);
    attn128_kernel<<<ATTN_B, 128>>>(b2);
    // 8: BN2 stats
    bnstats_kernel<<<HGB, 128>>>();
    // 9-10: layer 3
    gemm_hmma<64><<<HGB, 256, SMEM3>>>(W3, a3_src, a3_dst, g2, be2);
    attn64_kernel<<<ATTN_B, 128>>>(b3);
    // 11: fused readout
    pool_final_kernel<<<N_GRAPHS, 128>>>(fc1_w, fc1_b, fc2_w, fc2_b, out);
}

// round 17
// speedup vs baseline: 1.1019x; 1.1019x over previous
#include <cuda_runtime.h>
#include <cuda_fp16.h>
#include <cstdint>

#define N_NODES 100000
#define N_EDGES 1600000
#define E_TOT   (N_EDGES + N_NODES)   // self loops appended
#define N_GRAPHS 1024
#define EPS_BN 1e-5f
#define SCAN_B 98                      // ceil(N_NODES / 1024)
#define FILL_B ((E_TOT + 255) / 256)   // 6642
#define G1B    ((N_NODES + 7) / 8)     // 12500
#define NB256  ((N_NODES + 255) / 256) // 391
#define FULLM 0xffffffffu
#define LOG2E 1.4426950408889634f

// ----------------------------- scratch (device globals) -----------------------------
__device__ int    g_batch[N_NODES];
__device__ int    g_deg[N_NODES];      // zero-initialized; scan re-zeroes after use
__device__ int    g_off[N_NODES + 1];
__device__ int    g_cur[N_NODES];
__device__ int    g_csr[E_TOT];
__device__ volatile unsigned g_agg[SCAN_B];
__device__ float  g_wals[40];              // folded W1@a1_src (20) | W1@a1_dst (20), xLOG2E
__device__ float  g_z[N_NODES * 32];       // layer-1 aggregated x per head (4x8, k<5 valid)
__device__ __half g_hlinh[N_NODES * 128];  // post-GEMM features, fp16 (attn gather input)
__device__ __half g_feath[N_NODES * 128];  // attn output layers 1-2, fp16 (BN/gemm input)
__device__ float  g_feat[N_NODES * 64];    // attn output layer 3, fp32 (pool input)
__device__ float  g_als[N_NODES * 4];      // pre-scaled by log2(e)
__device__ float  g_ald[N_NODES * 4];      // pre-scaled by log2(e)
__device__ float  g_bnsum[256];            // [0:128) sum, [128:256) sumsq

// ----------------------------- utility -----------------------------
__device__ __forceinline__ float ex2f(float x) {
    float r; asm("ex2.approx.f32 %0, %1;" : "=f"(r) : "f"(x)); return r;
}
__device__ __forceinline__ float eluf(float v) {
    return v > 0.f ? v : ex2f(v * LOG2E) - 1.f;
}
__device__ __forceinline__ float lrelu(float v) { return fmaxf(v, 0.2f * v); }
__device__ __forceinline__ unsigned long long pack2(float x, float y) {
    unsigned long long r;
    asm("mov.b64 %0, {%1, %2};" : "=l"(r) : "f"(x), "f"(y));
    return r;
}
__device__ __forceinline__ float2 unpack2(unsigned long long v) {
    float2 r;
    asm("mov.b64 {%0, %1}, %2;" : "=f"(r.x), "=f"(r.y) : "l"(v));
    return r;
}
#define FMA_F32X2(acc, a, b) \
    asm("fma.rn.f32x2 %0, %1, %2, %0;" : "+l"(acc) : "l"(a), "l"(b))

__device__ __forceinline__ uint32_t smem_u32(const void* p) {
    return (uint32_t)__cvta_generic_to_shared(p);
}
__device__ __forceinline__ void ldmatrix_x4(uint32_t* r, uint32_t addr) {
    asm volatile("ldmatrix.sync.aligned.m8n8.x4.shared.b16 {%0,%1,%2,%3}, [%4];"
                 : "=r"(r[0]), "=r"(r[1]), "=r"(r[2]), "=r"(r[3]) : "r"(addr));
}
__device__ __forceinline__ void ldmatrix_x2t(uint32_t& b0, uint32_t& b1, uint32_t addr) {
    asm volatile("ldmatrix.sync.aligned.m8n8.x2.trans.shared.b16 {%0,%1}, [%2];"
                 : "=r"(b0), "=r"(b1) : "r"(addr));
}
__device__ __forceinline__ void mma16816(float& d0, float& d1, float& d2, float& d3,
                                         const uint32_t* a, uint32_t b0, uint32_t b1) {
    asm volatile("mma.sync.aligned.m16n8k16.row.col.f32.f16.f16.f32 "
                 "{%0,%1,%2,%3}, {%4,%5,%6,%7}, {%8,%9}, {%0,%1,%2,%3};"
                 : "+f"(d0), "+f"(d1), "+f"(d2), "+f"(d3)
                 : "r"(a[0]), "r"(a[1]), "r"(a[2]), "r"(a[3]), "r"(b0), "r"(b1));
}

// Per-block dtype detect + edge decode (int64 with values < 2^31: odd int32 words are 0).
__device__ __forceinline__ int detect_is64_block(const void* ei, int i) {
    __shared__ int s_is64;
    if (threadIdx.x == 0) s_is64 = 1;
    __syncthreads();
    if (i < N_EDGES) {
        if (((const int*)ei)[2 * i + 1] != 0) s_is64 = 0;   // race-benign
    }
    __syncthreads();
    return s_is64;
}
__device__ __forceinline__ void decode_edge(const void* ei, int i, int is64, int& s, int& d) {
    if (i < N_EDGES) {
        if (is64) {
            s = (int)((const long long*)ei)[i];
            d = (int)((const long long*)ei)[N_EDGES + i];
        } else {
            s = ((const int*)ei)[i];
            d = ((const int*)ei)[N_EDGES + i];
        }
    } else {
        s = d = i - N_EDGES;
    }
}

// ----------------------------- count: degree + batch + folded layer-1 attn weights ----------
__global__ void count_kernel(const void* ei, const void* batch,
                             const float* __restrict__ W1,
                             const float* __restrict__ aS, const float* __restrict__ aD) {
    int i = blockIdx.x * 256 + threadIdx.x;
    int is64 = detect_is64_block(ei, i);
    if (blockIdx.x == 0) {
        if (threadIdx.x < SCAN_B) g_agg[threadIdx.x] = 0u;
        if (threadIdx.x < 40) {
            int t = threadIdx.x;
            const float* av = (t < 20) ? aS : aD;
            int tt = t % 20;
            int k = tt >> 2, h = tt & 3;
            float w = 0.f;
            for (int c = 0; c < 32; c++)
                w += __ldg(&W1[k * 128 + h * 32 + c]) * __ldg(&av[h * 32 + c]);
            g_wals[t] = w * LOG2E;
        }
    }
    if (i < E_TOT) {
        int s, d;
        decode_edge(ei, i, is64, s, d);
        (void)s;
        atomicAdd(&g_deg[d], 1);
    }
    if (i < N_NODES) {
        g_batch[i] = is64 ? (int)((const long long*)batch)[i] : ((const int*)batch)[i];
    }
}

// ----------------------------- single-pass exclusive scan (decoupled lookback) --------------
__global__ void scan_onepass() {
    __shared__ int wsum[32];
    __shared__ int part[128];
    int b = blockIdx.x, t = threadIdx.x;
    int i = b * 1024 + t;
    int d = (i < N_NODES) ? g_deg[i] : 0;
    int lane = t & 31, wid = t >> 5;
    int v = d;
#pragma unroll
    for (int o = 1; o < 32; o <<= 1) {
        int u = __shfl_up_sync(FULLM, v, o);
        if (lane >= o) v += u;
    }
    if (lane == 31) wsum[wid] = v;
    if (t < 128) part[t] = 0;
    __syncthreads();
    if (t < 32) {
        int w = wsum[t];
#pragma unroll
        for (int o = 1; o < 32; o <<= 1) {
            int u = __shfl_up_sync(FULLM, w, o);
            if (t >= o) w += u;
        }
        wsum[t] = w;
    }
    __syncthreads();
    int incl = v + (wid ? wsum[wid - 1] : 0);
    int total = wsum[31];
    if (t == 0) atomicExch((unsigned*)&g_agg[b], ((unsigned)total) | 0x80000000u);
    if (t < b) {
        unsigned x;
        do { x = g_agg[t]; } while (!(x & 0x80000000u));
        part[t] = (int)(x & 0x7fffffffu);
    }
    __syncthreads();
    if (t < 64) part[t] += part[t + 64]; __syncthreads();
    if (t < 32) part[t] += part[t + 32]; __syncthreads();
    if (t < 16) part[t] += part[t + 16]; __syncthreads();
    if (t < 8)  part[t] += part[t + 8];  __syncthreads();
    if (t < 4)  part[t] += part[t + 4];  __syncthreads();
    if (t < 2)  part[t] += part[t + 2];  __syncthreads();
    if (t < 1)  part[t] += part[t + 1];  __syncthreads();
    int base = part[0];
    if (i < N_NODES) {
        int excl = base + incl - d;
        g_off[i] = excl;
        g_cur[i] = excl;
        g_deg[i] = 0;
    }
    if (b == 0 && t == 0) g_off[N_NODES] = E_TOT;
}

// ----------------------------- fused CSR-fill + layer-1 logits (x @ folded weights) ---------
__global__ void fill_als1_kernel(const void* ei, const float* __restrict__ x) {
    if (blockIdx.x < FILL_B) {
        int i = blockIdx.x * 256 + threadIdx.x;
        int is64 = detect_is64_block(ei, i);
        if (i < E_TOT) {
            int s, d;
            decode_edge(ei, i, is64, s, d);
            int p = atomicAdd(&g_cur[d], 1);
            g_csr[p] = s;
        }
        return;
    }
    int n = (blockIdx.x - FILL_B) * 256 + threadIdx.x;
    if (n >= N_NODES) return;
    float xv[5];
#pragma unroll
    for (int k = 0; k < 5; k++) xv[k] = __ldg(&x[n * 5 + k]);
    float als_[4], ald_[4];
#pragma unroll
    for (int h = 0; h < 4; h++) {
        float aS = 0.f, aD = 0.f;
#pragma unroll
        for (int k = 0; k < 5; k++) {
            aS += xv[k] * g_wals[k * 4 + h];
            aD += xv[k] * g_wals[20 + k * 4 + h];
        }
        als_[h] = aS;
        ald_[h] = aD;
    }
    *(float4*)(g_als + n * 4) = make_float4(als_[0], als_[1], als_[2], als_[3]);
    *(float4*)(g_ald + n * 4) = make_float4(ald_[0], ald_[1], ald_[2], ald_[3]);
}

// ----------------------------- layer-1 attention over raw x (rank-5 trick) -------------------
// warp per node; lane = (h = lane>>3, k = lane&7), k<5 valid. One edge per warp-step,
// 4-deep batches for MLP. z[n, h*8+k] = (Σ_src α_h x_src[k]).  No cross-lane reduction.
__global__ void __launch_bounds__(128, 12) attn1x_kernel(const float* __restrict__ x) {
    if (blockIdx.x == 0 && threadIdx.x < 128) {
        g_bnsum[threadIdx.x] = 0.f;
        g_bnsum[threadIdx.x + 128] = 0.f;
    }
    int node = (blockIdx.x * blockDim.x + threadIdx.x) >> 5;
    int lane = threadIdx.x & 31;
    if (node >= N_NODES) return;
    const int h = lane >> 3;
    const int k = lane & 7;
    const bool kv = k < 5;

    float ad = g_ald[node * 4 + h];
    float s = 0.f, acc = 0.f;
    const float* ab = g_als + h;

    int beg = g_off[node], end = g_off[node + 1];
    int i = beg;
    for (; i + 4 <= end; i += 4) {
        int src[4]; float al[4], xv[4];
#pragma unroll
        for (int t = 0; t < 4; t++) src[t] = __ldg(&g_csr[i + t]);
#pragma unroll
        for (int t = 0; t < 4; t++) al[t] = __ldg(ab + src[t] * 4);
#pragma unroll
        for (int t = 0; t < 4; t++) xv[t] = kv ? __ldg(&x[src[t] * 5 + k]) : 0.f;
#pragma unroll
        for (int t = 0; t < 4; t++) {
            float p = ex2f(lrelu(al[t] + ad));
            s += p;
            acc += p * xv[t];
        }
    }
    for (; i < end; i++) {
        int src = __ldg(&g_csr[i]);
        float a = __ldg(ab + src * 4);
        float p = ex2f(lrelu(a + ad));
        s += p;
        float xv = kv ? __ldg(&x[src * 5 + k]) : 0.f;
        acc += p * xv;
    }
    float inv = 1.f / (s + 1e-16f);
    g_z[(size_t)node * 32 + lane] = acc * inv;
}

// ----------------------------- expand: g_feath = z @ W1 (per head) + b1 ----------------------
__global__ void expand1_kernel(const float* __restrict__ W1, const float* __restrict__ b1) {
    int node = blockIdx.x * 8 + (threadIdx.x >> 5);
    int lane = threadIdx.x & 31;
    if (node >= N_NODES) return;
    float z = g_z[(size_t)node * 32 + lane];
    int h = lane >> 3;
    float zk[5];
#pragma unroll
    for (int kk = 0; kk < 5; kk++) zk[kk] = __shfl_sync(FULLM, z, h * 8 + kk);
    int c = lane * 4;
    float4 acc = __ldg((const float4*)(b1 + c));
#pragma unroll
    for (int kk = 0; kk < 5; kk++) {
        float4 w = __ldg((const float4*)(W1 + kk * 128 + c));
        acc.x += zk[kk] * w.x;
        acc.y += zk[kk] * w.y;
        acc.z += zk[kk] * w.z;
        acc.w += zk[kk] * w.w;
    }
    __half2 ha = __floats2half2_rn(acc.x, acc.y);
    __half2 hb = __floats2half2_rn(acc.z, acc.w);
    uint2 st;
    st.x = *(unsigned*)&ha; st.y = *(unsigned*)&hb;
    *(uint2*)(g_feath + (size_t)node * 128 + c) = st;
}

// ----------------------------- 128 -> OUTC GEMM via HMMA (tensor cores) ----------------------
template <int OUTC>
__global__ void __launch_bounds__(256) gemm_hmma(
        const float* __restrict__ W,
        const float* __restrict__ aS, const float* __restrict__ aD,
        const float* __restrict__ bnG, const float* __restrict__ bnBe) {
    constexpr int NT = OUTC / 8;
    constexpr int H  = (OUTC == 128) ? 4 : 1;
    constexpr int SA_STR = 136;
    constexpr int SB_STR = OUTC + 8;

    extern __shared__ char smem[];
    __half* sA = (__half*)smem;
    __half* sB = sA + 128 * SA_STR;
    float* sScale = (float*)(sB + 128 * SB_STR);
    float* sShift = sScale + 128;
    float* sAS = sShift + 128;
    float* sAD = sAS + 128;

    int t = threadIdx.x;
    int warp = t >> 5, lane = t & 31;
    int nodeBase = blockIdx.x * 128;

    if (t < 128) {
        const float invN = 1.f / (float)N_NODES;
        float mu = g_bnsum[t] * invN;
        float var = g_bnsum[128 + t] * invN - mu * mu;
        float rs = rsqrtf(var + EPS_BN);
        float sc = rs * __ldg(&bnG[t]);
        sScale[t] = sc;
        sShift[t] = __ldg(&bnBe[t]) - mu * sc;
    }
    if (t < OUTC) {
        sAS[t] = __ldg(&aS[t]);
        sAD[t] = __ldg(&aD[t]);
    }
    __syncthreads();

#pragma unroll
    for (int j = 0; j < 64; j++) {
        int idx = t + j * 256;
        int row = idx >> 7, col = idx & 127;
        int node = nodeBase + row;
        float v = 0.f;
        if (node < N_NODES)
            v = eluf(__half2float(g_feath[node * 128 + col]) * sScale[col] + sShift[col]);
        sA[row * SA_STR + col] = __float2half_rn(v);
    }
#pragma unroll
    for (int j = 0; j < (128 * OUTC) / 256; j++) {
        int idx = t + j * 256;
        int k = idx / OUTC, n = idx % OUTC;
        sB[k * SB_STR + n] = __float2half_rn(__ldg(&W[idx]));
    }
    __syncthreads();

    uint32_t afr[8][4];
    {
        int arow = warp * 16 + (lane & 15);
        int acol = (lane >> 4) << 3;
#pragma unroll
        for (int k8 = 0; k8 < 8; k8++) {
            uint32_t addr = smem_u32(&sA[arow * SA_STR + k8 * 16 + acol]);
            ldmatrix_x4(afr[k8], addr);
        }
    }

    float sS0[H], sS8[H], sD0[H], sD8[H];
#pragma unroll
    for (int h = 0; h < H; h++) { sS0[h] = 0.f; sS8[h] = 0.f; sD0[h] = 0.f; sD8[h] = 0.f; }

    int r = lane >> 2;
    int n0 = nodeBase + warp * 16 + r;
    int brow = lane & 15;

#pragma unroll
    for (int nt = 0; nt < NT; nt++) {
        float d0 = 0.f, d1 = 0.f, d2 = 0.f, d3 = 0.f;
#pragma unroll
        for (int k8 = 0; k8 < 8; k8++) {
            uint32_t b0, b1;
            uint32_t addr = smem_u32(&sB[(k8 * 16 + brow) * SB_STR + nt * 8]);
            ldmatrix_x2t(b0, b1, addr);
            mma16816(d0, d1, d2, d3, afr[k8], b0, b1);
        }
        int c = nt * 8 + 2 * (lane & 3);
        if (n0 < N_NODES)
            *(__half2*)(g_hlinh + (size_t)n0 * OUTC + c) = __floats2half2_rn(d0, d1);
        if (n0 + 8 < N_NODES)
            *(__half2*)(g_hlinh + (size_t)(n0 + 8) * OUTC + c) = __floats2half2_rn(d2, d3);
        int h = (OUTC == 128) ? (nt >> 2) : 0;
        float as0 = sAS[c], as1 = sAS[c + 1];
        float ad0 = sAD[c], ad1 = sAD[c + 1];
        sS0[h] += d0 * as0 + d1 * as1;
        sS8[h] += d2 * as0 + d3 * as1;
        sD0[h] += d0 * ad0 + d1 * ad1;
        sD8[h] += d2 * ad0 + d3 * ad1;
    }

#pragma unroll
    for (int h = 0; h < H; h++) {
#pragma unroll
        for (int o = 1; o < 4; o <<= 1) {
            sS0[h] += __shfl_xor_sync(FULLM, sS0[h], o);
            sS8[h] += __shfl_xor_sync(FULLM, sS8[h], o);
            sD0[h] += __shfl_xor_sync(FULLM, sD0[h], o);
            sD8[h] += __shfl_xor_sync(FULLM, sD8[h], o);
        }
    }
    if ((lane & 3) == 0) {
        if (n0 < N_NODES) {
#pragma unroll
            for (int h = 0; h < H; h++) {
                g_als[n0 * H + h] = sS0[h] * LOG2E;
                g_ald[n0 * H + h] = sD0[h] * LOG2E;
            }
        }
        if (n0 + 8 < N_NODES) {
#pragma unroll
            for (int h = 0; h < H; h++) {
                g_als[(n0 + 8) * H + h] = sS8[h] * LOG2E;
                g_ald[(n0 + 8) * H + h] = sD8[h] * LOG2E;
            }
        }
    }
}

// ----------------------------- GAT aggregation (R14 proven form; layers 2-3) -----------------
template <int H, int HC, bool ELU_OUT>
__global__ void __launch_bounds__(128, 12) attn_kernel(const float* __restrict__ bias) {
    if (blockIdx.x == 0 && threadIdx.x < 128) {
        g_bnsum[threadIdx.x] = 0.f;
        g_bnsum[threadIdx.x + 128] = 0.f;
    }
    constexpr int K = HC / 16;           // channels per lane (8 or 4)
    constexpr int KP = K / 2;            // packed f32x2 accumulators
    constexpr int C = HC / H;
    int node = (blockIdx.x * blockDim.x + threadIdx.x) >> 5;
    int lane = threadIdx.x & 31;
    if (node >= N_NODES) return;
    const int sub = lane >> 4;           // 0: even edges, 1: odd edges
    const int li = lane & 15;
    const int h0 = (li * K) / C;

    float ad = g_ald[node * H + h0];
    float s = 0.f;
    unsigned long long acc2[KP];
#pragma unroll
    for (int j = 0; j < KP; j++) acc2[j] = 0ull;

    const char* fb = (const char*)g_hlinh + li * (K * 2);
    const float* ab = g_als + h0;

    int beg = g_off[node], end = g_off[node + 1];
    int i = beg;
    for (; i + 8 <= end; i += 8) {
        int src[4]; float al[4];
        uint4 q4[4]; uint2 q2[4];
#pragma unroll
        for (int t = 0; t < 4; t++) src[t] = __ldg(&g_csr[i + 2 * t + sub]);
#pragma unroll
        for (int t = 0; t < 4; t++) al[t] = __ldg(ab + src[t] * H);
#pragma unroll
        for (int t = 0; t < 4; t++) {
            if (K == 8) q4[t] = *(const uint4*)(fb + (size_t)src[t] * (HC * 2));
            else        q2[t] = *(const uint2*)(fb + (size_t)src[t] * (HC * 2));
        }
#pragma unroll
        for (int t = 0; t < 4; t++) {
            float p = ex2f(lrelu(al[t] + ad));
            s += p;
            unsigned long long pk = pack2(p, p);
            const __half2* hq = (K == 8) ? (const __half2*)&q4[t] : (const __half2*)&q2[t];
#pragma unroll
            for (int j = 0; j < KP; j++) {
                float2 f = __half22float2(hq[j]);
                FMA_F32X2(acc2[j], pk, pack2(f.x, f.y));
            }
        }
    }
    for (; i < end; i += 2) {
        int idx = i + sub;
        bool valid = idx < end;
        int src = __ldg(&g_csr[valid ? idx : end - 1]);
        float a = __ldg(ab + src * H);
        float p = ex2f(lrelu(a + ad));
        p = valid ? p : 0.f;
        s += p;
        unsigned long long pk = pack2(p, p);
        uint4 q4; uint2 q2;
        if (K == 8) q4 = *(const uint4*)(fb + (size_t)src * (HC * 2));
        else        q2 = *(const uint2*)(fb + (size_t)src * (HC * 2));
        const __half2* hq = (K == 8) ? (const __half2*)&q4 : (const __half2*)&q2;
#pragma unroll
        for (int j = 0; j < KP; j++) {
            float2 f = __half22float2(hq[j]);
            FMA_F32X2(acc2[j], pk, pack2(f.x, f.y));
        }
    }

    s += __shfl_xor_sync(FULLM, s, 16);
    float accf[K];
#pragma unroll
    for (int j = 0; j < KP; j++) {
        float2 f = unpack2(acc2[j]);
        f.x += __shfl_xor_sync(FULLM, f.x, 16);
        f.y += __shfl_xor_sync(FULLM, f.y, 16);
        accf[2 * j] = f.x;
        accf[2 * j + 1] = f.y;
    }
    float inv = 1.f / (s + 1e-16f);

    if (K == 8) {
        int cb = li * 8 + sub * 4;
        float4 bv = __ldg((const float4*)(bias + cb));
        float4 o;
        o.x = (sub ? accf[4] : accf[0]) * inv + bv.x;
        o.y = (sub ? accf[5] : accf[1]) * inv + bv.y;
        o.z = (sub ? accf[6] : accf[2]) * inv + bv.z;
        o.w = (sub ? accf[7] : accf[3]) * inv + bv.w;
        __half2 ha = __floats2half2_rn(o.x, o.y);
        __half2 hb = __floats2half2_rn(o.z, o.w);
        uint2 st;
        st.x = *(unsigned*)&ha; st.y = *(unsigned*)&hb;
        *(uint2*)(g_feath + (size_t)node * HC + cb) = st;
    } else {
        int cb = li * 4 + sub * 2;
        float2 bv = __ldg((const float2*)(bias + cb));
        float2 o;
        o.x = (sub ? accf[2] : accf[0]) * inv + bv.x;
        o.y = (sub ? accf[3] : accf[1]) * inv + bv.y;
        if (ELU_OUT) { o.x = eluf(o.x); o.y = eluf(o.y); }
        *(float2*)(g_feat + (size_t)node * HC + cb) = o;
    }
}

// ----------------------------- batch norm stats (fp16 input; bnsum zeroed by attn) ----------
__global__ void bnstats_kernel() {
    int c = threadIdx.x;  // 128
    int n0 = blockIdx.x * 128;
    float s = 0.f, sq = 0.f;
    for (int r = 0; r < 128; r++) {
        int n = n0 + r;
        if (n < N_NODES) {
            float v = __half2float(g_feath[n * 128 + c]);
            s += v;
            sq += v * v;
        }
    }
    atomicAdd(&g_bnsum[c], s);
    atomicAdd(&g_bnsum[128 + c], sq);
}

// ----------------------------- fused pooling + classifier (batch sorted) ---------------------
__device__ __forceinline__ int lower_bound_batch(int key) {
    int lo = 0, hi = N_NODES;
    while (lo < hi) {
        int mid = (lo + hi) >> 1;
        if (g_batch[mid] < key) lo = mid + 1;
        else hi = mid;
    }
    return lo;
}

__global__ void pool_final_kernel(const float* __restrict__ fc1w, const float* __restrict__ fc1b,
                                  const float* __restrict__ fc2w, const float* __restrict__ fc2b,
                                  float* __restrict__ out) {
    int gidx = blockIdx.x;
    __shared__ int se[2];
    if (threadIdx.x < 2) se[threadIdx.x] = lower_bound_batch(gidx + threadIdx.x);
    __syncthreads();
    int beg = se[0], end = se[1];
    int c = threadIdx.x & 63, sl = threadIdx.x >> 6;
    float sum = 0.f, mx = __int_as_float(0xff800000);
    for (int n = beg + sl; n < end; n += 2) {
        float v = g_feat[n * 64 + c];
        sum += v;
        mx = fmaxf(mx, v);
    }
    __shared__ float shs[128], shm[128], hg[128];
    shs[threadIdx.x] = sum;
    shm[threadIdx.x] = mx;
    __syncthreads();
    if (sl == 0) {
        sum += shs[64 + c];
        mx = fmaxf(mx, shm[64 + c]);
        int cnt = end - beg;
        hg[c] = (cnt > 0) ? sum / (float)cnt : 0.f;
        hg[64 + c] = (cnt > 0) ? mx : 0.f;
    }
    __syncthreads();
    __shared__ float warpsum[2];
    if (threadIdx.x < 64) {
        int c2 = threadIdx.x;
        float acc = __ldg(&fc1b[c2]);
#pragma unroll 8
        for (int k = 0; k < 128; k++) acc += hg[k] * __ldg(&fc1w[k * 64 + c2]);
        float z = eluf(acc);
        float part = z * __ldg(&fc2w[c2]);
#pragma unroll
        for (int off = 16; off; off >>= 1) part += __shfl_xor_sync(FULLM, part, off);
        if ((c2 & 31) == 0) warpsum[c2 >> 5] = part;
    }
    __syncthreads();
    if (threadIdx.x == 0) out[gidx] = warpsum[0] + warpsum[1] + __ldg(&fc2b[0]);
}

// ----------------------------- launch -----------------------------
extern "C" void kernel_launch(void* const* d_in, const int* in_sizes, int n_in,
                              void* d_out, int out_size) {
    const float* x      = (const float*)d_in[0];
    const void*  ei     = d_in[1];
    const void*  batch  = d_in[2];
    const float* W1     = (const float*)d_in[3];
    const float* a1_src = (const float*)d_in[4];
    const float* a1_dst = (const float*)d_in[5];
    const float* b1     = (const float*)d_in[6];
    const float* g1     = (const float*)d_in[7];
    const float* be1    = (const float*)d_in[8];
    const float* W2     = (const float*)d_in[9];
    const float* a2_src = (const float*)d_in[10];
    const float* a2_dst = (const float*)d_in[11];
    const float* b2     = (const float*)d_in[12];
    const float* g2     = (const float*)d_in[13];
    const float* be2    = (const float*)d_in[14];
    const float* W3     = (const float*)d_in[15];
    const float* a3_src = (const float*)d_in[16];
    const float* a3_dst = (const float*)d_in[17];
    const float* b3     = (const float*)d_in[18];
    const float* fc1_w  = (const float*)d_in[19];
    const float* fc1_b  = (const float*)d_in[20];
    const float* fc2_w  = (const float*)d_in[21];
    const float* fc2_b  = (const float*)d_in[22];
    float* out = (float*)d_out;

    const int ATTN_B = (N_NODES + 3) / 4;   // 128-thr blocks, 4 warps = 4 nodes/block
    const int HGB = (N_NODES + 127) / 128;

    const int SMEM2 = (128 * 136 + 128 * (128 + 8)) * 2 + 4 * 128 * 4;  // 71680
    const int SMEM3 = (128 * 136 + 128 * (64 + 8)) * 2 + 4 * 128 * 4;   // 55296
    cudaFuncSetAttribute(gemm_hmma<128>, cudaFuncAttributeMaxDynamicSharedMemorySize, SMEM2);
    cudaFuncSetAttribute(gemm_hmma<64>,  cudaFuncAttributeMaxDynamicSharedMemorySize, SMEM3);

    // 1: degree count + batch convert + folded layer-1 attn weights
    count_kernel<<<FILL_B, 256>>>(ei, batch, W1, a1_src, a1_dst);
    // 2: single-pass offsets scan (+deg re-zero)
    scan_onepass<<<SCAN_B, 1024>>>();
    // 3: CSR fill + layer-1 logits from raw x
    fill_als1_kernel<<<FILL_B + NB256, 256>>>(ei, x);
    // 4: layer-1 attention over raw x (rank-5 trick)  <-- ncu capture slot
    attn1x_kernel<<<ATTN_B, 128>>>(x);
    // 5: expand z @ W1 + b1 -> g_feath
    expand1_kernel<<<G1B, 256>>>(W1, b1);
    // 6: BN1 stats
    bnstats_kernel<<<HGB, 128>>>();
    // 7-8: layer 2
    gemm_hmma<128><<<HGB, 256, SMEM2>>>(W2, a2_src, a2_dst, g1, be1);
    attn_kernel<4, 128, false><<<ATTN_B, 128>>>(b2);
    // 9: BN2 stats
    bnstats_kernel<<<HGB, 128>>>();
    // 10-11: layer 3
    gemm_hmma<64><<<HGB, 256, SMEM3>>>(W3, a3_src, a3_dst, g2, be2);
    attn_kernel<1, 64, true><<<ATTN_B, 128>>>(b3);
    // 12: fused readout
    pool_final_kernel<<<N_GRAPHS, 128>>>(fc1_w, fc1_b, fc2_w, fc2_b, out);
}